// round 13
// baseline (speedup 1.0000x reference)
#include <cuda_runtime.h>
#include <cuda_bf16.h>
#include <math.h>

// Problem constants
#define BB   32
#define INF  128
#define HH   1024
#define OUTF 128
#define KCAT (INF + HH)   // 1152
#define TPB  256
#define RPB  8            // rows (warps) per block
#define NCH  3            // chains: 11 / 11 / 10 batches

// Scratch (allocation-free rule: __device__ globals)
__device__ float g_c0[BB * HH];
__device__ float g_c1[BB * HH];
__device__ float g_c2[BB * HH];
__device__ float g_logits[BB * OUTF];

// ---------------------------------------------------------------------------
// R2/R7-proven matvec tile kernel: 8 warps/block = 8 consecutive rows of ONE
// batch; activation staged in smem once; W front-batched with __ldcs; tanh.
// ---------------------------------------------------------------------------
template <int K, bool LAYER0>
__global__ __launch_bounds__(TPB) void matvec_kernel(
    const float* __restrict__ W, const float* __restrict__ bias,
    const float* __restrict__ in0,   // LAYER0: x ; else: activations [B,K]
    const float* __restrict__ in1,   // LAYER0: hidden ; else unused
    float* __restrict__ out, int Hout, int row_off)
{
    __shared__ float4 xs[K / 4];

    const int rowbase = row_off + blockIdx.x * RPB;
    const int b = rowbase / Hout;

    if (LAYER0) {
        const float4* xv = reinterpret_cast<const float4*>(in0 + (size_t)b * INF);
        const float4* hv = reinterpret_cast<const float4*>(in1 + (size_t)b * HH);
#pragma unroll
        for (int i = threadIdx.x; i < K / 4; i += TPB)
            xs[i] = (i < INF / 4) ? xv[i] : hv[i - INF / 4];
    } else {
        const float4* src = reinterpret_cast<const float4*>(in0 + (size_t)b * K);
#pragma unroll
        for (int i = threadIdx.x; i < K / 4; i += TPB)
            xs[i] = src[i];
    }
    __syncthreads();

    const int warp = threadIdx.x >> 5;
    const int lane = threadIdx.x & 31;
    const int row  = rowbase + warp;
    const int o    = row - b * Hout;

    const float4* __restrict__ Wr = reinterpret_cast<const float4*>(W + (size_t)row * K);
    constexpr int NIT = K / 128;

    float4 w[NIT];
#pragma unroll
    for (int j = 0; j < NIT; j++)
        w[j] = __ldcs(Wr + j * 32 + lane);

    float sum = 0.f;
#pragma unroll
    for (int j = 0; j < NIT; j++) {
        float4 v = xs[j * 32 + lane];
        sum += w[j].x * v.x + w[j].y * v.y + w[j].z * v.z + w[j].w * v.w;
    }
#pragma unroll
    for (int off = 16; off; off >>= 1)
        sum += __shfl_xor_sync(0xFFFFFFFFu, sum, off);

    if (lane == 0)
        out[row] = tanhf(sum + bias[o]);
}

// Fused heads (runtime batch count): Wo tiles FIRST (blocks [0, NBO) -> logits,
// feeding the dependent softmax early), then Wh tiles (tanh -> new_hidden).
__global__ __launch_bounds__(TPB) void heads_kernel(
    const float* __restrict__ Wh, const float* __restrict__ bh,
    const float* __restrict__ Wo, const float* __restrict__ bo,
    float* __restrict__ new_hidden_out, int boff, int nbatch)
{
    __shared__ float4 xs[HH / 4];

    const int NBO = (nbatch * OUTF) / RPB;
    const bool is_o = ((int)blockIdx.x < NBO);
    int rowbase, b, Hout;
    const float* Wbase; const float* bias;
    if (is_o) { rowbase = boff * OUTF + blockIdx.x * RPB;         Hout = OUTF; Wbase = Wo; bias = bo; }
    else      { rowbase = boff * HH   + (blockIdx.x - NBO) * RPB; Hout = HH;   Wbase = Wh; bias = bh; }
    b = rowbase / Hout;

    {
        const float4* src = reinterpret_cast<const float4*>(g_c2 + (size_t)b * HH);
#pragma unroll
        for (int i = threadIdx.x; i < HH / 4; i += TPB)
            xs[i] = src[i];
    }
    __syncthreads();

    const int warp = threadIdx.x >> 5;
    const int lane = threadIdx.x & 31;
    const int row  = rowbase + warp;
    const int o    = row - b * Hout;

    const float4* __restrict__ Wr = reinterpret_cast<const float4*>(Wbase + (size_t)row * HH);
    constexpr int NIT = HH / 128;

    float4 w[NIT];
#pragma unroll
    for (int j = 0; j < NIT; j++)
        w[j] = __ldcs(Wr + j * 32 + lane);

    float sum = 0.f;
#pragma unroll
    for (int j = 0; j < NIT; j++) {
        float4 v = xs[j * 32 + lane];
        sum += w[j].x * v.x + w[j].y * v.y + w[j].z * v.z + w[j].w * v.w;
    }
#pragma unroll
    for (int off = 16; off; off >>= 1)
        sum += __shfl_xor_sync(0xFFFFFFFFu, sum, off);

    if (lane == 0) {
        if (is_o) g_logits[row] = sum + bias[o];
        else      new_hidden_out[row] = tanhf(sum + bias[o]);
    }
}

// log_softmax for batches [boff, boff+nwarps); one warp per batch.
__global__ void log_softmax_kernel(float* __restrict__ out, int boff) {
    const int warp = threadIdx.x >> 5;
    const int lane = threadIdx.x & 31;
    const int bq = boff + warp;
    const float* l = g_logits + bq * OUTF;

    float v[4];
#pragma unroll
    for (int i = 0; i < 4; i++) v[i] = l[i * 32 + lane];

    float m = fmaxf(fmaxf(v[0], v[1]), fmaxf(v[2], v[3]));
#pragma unroll
    for (int off = 16; off; off >>= 1)
        m = fmaxf(m, __shfl_xor_sync(0xFFFFFFFFu, m, off));

    float s = 0.f;
#pragma unroll
    for (int i = 0; i < 4; i++) s += __expf(v[i] - m);
#pragma unroll
    for (int off = 16; off; off >>= 1)
        s += __shfl_xor_sync(0xFFFFFFFFu, s, off);

    float lse = m + logf(s);
#pragma unroll
    for (int i = 0; i < 4; i++)
        out[bq * OUTF + i * 32 + lane] = v[i] - lse;
}

extern "C" void kernel_launch(void* const* d_in, const int* in_sizes, int n_in,
                              void* d_out, int out_size) {
    const float* x      = (const float*)d_in[0];
    const float* hidden = (const float*)d_in[1];
    const float* W0 = (const float*)d_in[2];
    const float* b0 = (const float*)d_in[3];
    const float* W1 = (const float*)d_in[4];
    const float* b1 = (const float*)d_in[5];
    const float* W2 = (const float*)d_in[6];
    const float* b2 = (const float*)d_in[7];
    const float* Wh = (const float*)d_in[8];
    const float* bh = (const float*)d_in[9];
    const float* Wo = (const float*)d_in[10];
    const float* bo = (const float*)d_in[11];

    float* out = (float*)d_out;                 // [B*OUT] log_softmax, then [B*H] new_hidden
    float* new_hidden = out + BB * OUTF;

    float *c0, *c1, *c2;
    cudaGetSymbolAddress((void**)&c0, g_c0);
    cudaGetSymbolAddress((void**)&c1, g_c1);
    cudaGetSymbolAddress((void**)&c2, g_c2);

    // Two side streams + fork/join events (R12-proven pattern).
    static cudaStream_t st[NCH - 1] = {};
    static cudaEvent_t evFork = nullptr, evJoin[NCH - 1] = {};
    if (!st[0]) {
        for (int i = 0; i < NCH - 1; i++) {
            cudaStreamCreateWithFlags(&st[i], cudaStreamNonBlocking);
            cudaEventCreateWithFlags(&evJoin[i], cudaEventDisableTiming);
        }
        cudaEventCreateWithFlags(&evFork, cudaEventDisableTiming);
    }

    // Chain batch partitions: 11 / 11 / 10
    const int nbat[NCH] = {11, 11, 10};
    const int boff[NCH] = {0, 11, 22};
    cudaStream_t cs[NCH] = {(cudaStream_t)0, st[0], st[1]};
    int blksL[NCH], blksH[NCH], roff[NCH];
    for (int ch = 0; ch < NCH; ch++) {
        blksL[ch] = (nbat[ch] * HH) / RPB;
        blksH[ch] = blksL[ch] + (nbat[ch] * OUTF) / RPB;
        roff[ch]  = boff[ch] * HH;
    }

    // Fork side chains off the capture (default) stream.
    cudaEventRecord(evFork, 0);
    for (int i = 0; i < NCH - 1; i++)
        cudaStreamWaitEvent(st[i], evFork, 0);

    // Breadth-first (interleaved) issue: all L0s, then all L1s, ... so
    // simultaneously-ready graph nodes alternate across chains.
    for (int ch = 0; ch < NCH; ch++)
        matvec_kernel<KCAT, true ><<<blksL[ch], TPB, 0, cs[ch]>>>(W0, b0, x,  hidden,  c0, HH, roff[ch]);
    for (int ch = 0; ch < NCH; ch++)
        matvec_kernel<HH,   false><<<blksL[ch], TPB, 0, cs[ch]>>>(W1, b1, c0, nullptr, c1, HH, roff[ch]);
    for (int ch = 0; ch < NCH; ch++)
        matvec_kernel<HH,   false><<<blksL[ch], TPB, 0, cs[ch]>>>(W2, b2, c1, nullptr, c2, HH, roff[ch]);
    for (int ch = 0; ch < NCH; ch++)
        heads_kernel<<<blksH[ch], TPB, 0, cs[ch]>>>(Wh, bh, Wo, bo, new_hidden, boff[ch], nbat[ch]);
    for (int ch = 0; ch < NCH; ch++)
        log_softmax_kernel<<<1, nbat[ch] * 32, 0, cs[ch]>>>(out, boff[ch]);

    // Join side chains back to the capture stream.
    for (int i = 0; i < NCH - 1; i++) {
        cudaEventRecord(evJoin[i], st[i]);
        cudaStreamWaitEvent(0, evJoin[i], 0);
    }

    (void)in_sizes; (void)n_in; (void)out_size;
}